// round 5
// baseline (speedup 1.0000x reference)
#include <cuda_runtime.h>
#include <cuda_bf16.h>
#include <cstdint>
#include <cstddef>

#define D_IN   96
#define D_OUT  256
#define MAXN   50000

// -------- scratch (device globals; no allocation allowed) --------
__device__ __align__(16) float g_agg[(size_t)MAXN * D_IN];    // 19.2 MB
__device__ __align__(16) float g_h[(size_t)MAXN * D_OUT];     // 51.2 MB
__device__ __align__(16) float g_w0r[D_IN * D_OUT];           // W0 tf32-rounded (same layout)
__device__ __align__(16) float g_w1r[D_OUT * D_OUT];          // W1 tf32-rounded
__device__ __align__(16) float g_scale[D_OUT];
__device__ __align__(16) float g_shift[D_OUT];

// ---------------- helpers ----------------
__device__ __forceinline__ uint32_t f2tf32(float f) {
    uint32_t u;
    asm("cvt.rna.tf32.f32 %0, %1;" : "=r"(u) : "f"(f));
    return u;
}
__device__ __forceinline__ float tf32f(float f) { return __uint_as_float(f2tf32(f)); }

__device__ __forceinline__ uint32_t smem_u32(const void* p) {
    uint32_t a;
    asm("{ .reg .u64 t; cvta.to.shared.u64 t, %1; cvt.u32.u64 %0, t; }"
        : "=r"(a) : "l"(p));
    return a;
}

__device__ __forceinline__ void mma_tf32(float d[4], const uint32_t a[4],
                                         const uint32_t b[2], const float c[4]) {
    asm volatile(
        "mma.sync.aligned.m16n8k8.row.col.f32.tf32.tf32.f32 "
        "{%0,%1,%2,%3}, {%4,%5,%6,%7}, {%8,%9}, {%10,%11,%12,%13};"
        : "=f"(d[0]), "=f"(d[1]), "=f"(d[2]), "=f"(d[3])
        : "r"(a[0]), "r"(a[1]), "r"(a[2]), "r"(a[3]),
          "r"(b[0]), "r"(b[1]),
          "f"(c[0]), "f"(c[1]), "f"(c[2]), "f"(c[3]));
}

// -------- kernel 0: agg = eps * x --------
__global__ void init_agg_kernel(const float* __restrict__ x,
                                const float* __restrict__ eps, int n4) {
    int i = blockIdx.x * blockDim.x + threadIdx.x;
    if (i >= n4) return;
    float e = eps[0];
    float4 xv = reinterpret_cast<const float4*>(x)[i];
    reinterpret_cast<float4*>(g_agg)[i] =
        make_float4(e * xv.x, e * xv.y, e * xv.z, e * xv.w);
}

// -------- vectorized global reduction (sm_90+) --------
__device__ __forceinline__ void red_add_v4(float* addr, float4 v) {
    asm volatile("red.global.add.v4.f32 [%0], {%1, %2, %3, %4};"
                 :: "l"(addr), "f"(v.x), "f"(v.y), "f"(v.z), "f"(v.w)
                 : "memory");
}

// -------- kernel 1: edge scatter  agg[dst] += vals * x[src] --------
__global__ void edge_scatter_kernel(const float* __restrict__ x,
                                    const int* __restrict__ src,
                                    const int* __restrict__ dst,
                                    const float* __restrict__ vals, int E) {
    int idx = blockIdx.x * blockDim.x + threadIdx.x;
    int e = idx / 24;
    if (e >= E) return;
    int c = idx - e * 24;
    int s = __ldg(src + e);
    int d = __ldg(dst + e);
    float v = __ldg(vals + e);
    float4 xv = __ldg(reinterpret_cast<const float4*>(x + (size_t)s * D_IN) + c);
    red_add_v4(g_agg + (size_t)d * D_IN + c * 4,
               make_float4(v * xv.x, v * xv.y, v * xv.z, v * xv.w));
}

// -------- kernel 1b: round agg to tf32 (rna) in place --------
__global__ void round_agg_kernel(int n4) {
    int i = blockIdx.x * blockDim.x + threadIdx.x;
    if (i >= n4) return;
    float4 v = reinterpret_cast<float4*>(g_agg)[i];
    reinterpret_cast<float4*>(g_agg)[i] =
        make_float4(tf32f(v.x), tf32f(v.y), tf32f(v.z), tf32f(v.w));
}

// -------- kernel 2: BN params + rounded weight copies --------
__global__ void bn_params_kernel(const float* __restrict__ gamma,
                                 const float* __restrict__ beta,
                                 const float* __restrict__ mean,
                                 const float* __restrict__ var) {
    int j = threadIdx.x;
    if (j < D_OUT) {
        float s = gamma[j] * rsqrtf(var[j] + 1e-3f);
        g_scale[j] = s;
        g_shift[j] = beta[j] - mean[j] * s;
    }
}
__global__ void prep_w_kernel(const float* __restrict__ W0,
                              const float* __restrict__ W1) {
    int t = blockIdx.x * blockDim.x + threadIdx.x;
    const int N0 = D_IN * D_OUT;
    if (t < N0)                      g_w0r[t] = tf32f(W0[t]);
    else if (t < N0 + D_OUT * D_OUT) g_w1r[t - N0] = tf32f(W1[t - N0]);
}

// ============== cp.async 3-stage pipelined TF32 mma.sync GEMM ==============
// C[M,Nn] = A[M,K] @ B[K,Nn]; A,B already tf32-rounded in gmem.
// Block 128x128, BK=32, 4 warps (2Mx2N) each 64x64. A in smem row-major
// [m][k] stride 36 (conflict-free: bank = 4*gid + ctig); B [k][n] stride 136
// (bank = 8*ctig + gid). cp.async 16B copies, 3 stages, 1 sync per step.

#define STAGES 3
#define SA 36
#define SB 136
#define A_BYTES (128 * SA * 4)              // 18432
#define B_BYTES (32 * SB * 4)               // 17408
#define STAGE_BYTES (A_BYTES + B_BYTES)     // 35840
#define GEMM_SMEM (STAGES * STAGE_BYTES)    // 107520

__device__ __forceinline__ void cp_async16(uint32_t dst, const void* src, uint32_t sz) {
    asm volatile("cp.async.cg.shared.global [%0], [%1], 16, %2;"
                 :: "r"(dst), "l"(src), "r"(sz) : "memory");
}
__device__ __forceinline__ void cp_commit() {
    asm volatile("cp.async.commit_group;" ::: "memory");
}

__global__ __launch_bounds__(128, 2) void pipe_gemm_kernel(
    const float* __restrict__ A, const float* __restrict__ B,
    float* __restrict__ C, int M, int Nn, int K,
    const float* __restrict__ scale, const float* __restrict__ shift,
    int relu, int round_out)
{
    extern __shared__ char smem[];
    const uint32_t sb = smem_u32(smem);

    const int tid  = threadIdx.x;
    const int lane = tid & 31;
    const int warp = tid >> 5;
    const int warpM = warp & 1;
    const int warpN = warp >> 1;
    const int gid  = lane >> 2;
    const int ctig = lane & 3;
    const int crow0 = blockIdx.y * 128;
    const int ccol0 = blockIdx.x * 128;

    float acc[4][8][4];
    #pragma unroll
    for (int mt = 0; mt < 4; mt++)
        #pragma unroll
        for (int nt = 0; nt < 8; nt++)
            #pragma unroll
            for (int i = 0; i < 4; i++) acc[mt][nt][i] = 0.f;

    auto copy_stage = [&](int s) {
        const int buf = s % STAGES;
        const uint32_t abase = sb + buf * STAGE_BYTES;
        const uint32_t bbase = abase + A_BYTES;
        const int k0 = s << 5;
        #pragma unroll
        for (int j = 0; j < 8; j++) {
            int id = tid + j * 128;
            int row = id >> 3, ch = id & 7;
            int gr = crow0 + row;
            int grc = gr < M ? gr : (M - 1);
            cp_async16(abase + (uint32_t)(row * SA + ch * 4) * 4,
                       A + (size_t)grc * K + k0 + ch * 4,
                       gr < M ? 16u : 0u);
        }
        #pragma unroll
        for (int j = 0; j < 8; j++) {
            int id = tid + j * 128;
            int row = id >> 5, ch = id & 31;
            cp_async16(bbase + (uint32_t)(row * SB + ch * 4) * 4,
                       B + (size_t)(k0 + row) * Nn + ccol0 + ch * 4, 16u);
        }
    };

    const int nst = K >> 5;   // K is 96 or 256 -> 3 or 8 steps
    copy_stage(0); cp_commit();
    copy_stage(1); cp_commit();

    for (int s = 0; s < nst; s++) {
        asm volatile("cp.async.wait_group 1;" ::: "memory");
        __syncthreads();
        if (s + 2 < nst) copy_stage(s + 2);
        cp_commit();

        const int buf = s % STAGES;
        const float* as = reinterpret_cast<const float*>(smem + buf * STAGE_BYTES);
        const float* bs = reinterpret_cast<const float*>(smem + buf * STAGE_BYTES + A_BYTES);

        #pragma unroll
        for (int ks = 0; ks < 4; ks++) {
            const int kk = ks * 8 + ctig;
            uint32_t af[4][4];
            #pragma unroll
            for (int mt = 0; mt < 4; mt++) {
                int m0 = warpM * 64 + mt * 16 + gid;
                af[mt][0] = __float_as_uint(as[m0 * SA + kk]);
                af[mt][1] = __float_as_uint(as[(m0 + 8) * SA + kk]);
                af[mt][2] = __float_as_uint(as[m0 * SA + kk + 4]);
                af[mt][3] = __float_as_uint(as[(m0 + 8) * SA + kk + 4]);
            }
            uint32_t bf[8][2];
            #pragma unroll
            for (int nt = 0; nt < 8; nt++) {
                int n0 = warpN * 64 + nt * 8 + gid;
                bf[nt][0] = __float_as_uint(bs[kk * SB + n0]);
                bf[nt][1] = __float_as_uint(bs[(kk + 4) * SB + n0]);
            }
            #pragma unroll
            for (int mt = 0; mt < 4; mt++)
                #pragma unroll
                for (int nt = 0; nt < 8; nt++)
                    mma_tf32(acc[mt][nt], af[mt], bf[nt], acc[mt][nt]);
        }
    }

    // -------- epilogue: optional BN + ReLU (+ tf32 rounding), store --------
    #pragma unroll
    for (int nt = 0; nt < 8; nt++) {
        int col = ccol0 + warpN * 64 + nt * 8 + 2 * ctig;
        float sc0 = 1.f, sc1 = 1.f, sh0 = 0.f, sh1 = 0.f;
        if (scale) {
            sc0 = __ldg(scale + col);     sc1 = __ldg(scale + col + 1);
            sh0 = __ldg(shift + col);     sh1 = __ldg(shift + col + 1);
        }
        #pragma unroll
        for (int mt = 0; mt < 4; mt++) {
            int row = crow0 + warpM * 64 + mt * 16 + gid;
            float v0 = acc[mt][nt][0], v1 = acc[mt][nt][1];
            float v2 = acc[mt][nt][2], v3 = acc[mt][nt][3];
            if (scale) {
                v0 = fmaf(v0, sc0, sh0); v1 = fmaf(v1, sc1, sh1);
                v2 = fmaf(v2, sc0, sh0); v3 = fmaf(v3, sc1, sh1);
            }
            if (relu) {
                v0 = fmaxf(v0, 0.f); v1 = fmaxf(v1, 0.f);
                v2 = fmaxf(v2, 0.f); v3 = fmaxf(v3, 0.f);
            }
            if (round_out) {
                v0 = tf32f(v0); v1 = tf32f(v1); v2 = tf32f(v2); v3 = tf32f(v3);
            }
            if (row < M)
                *reinterpret_cast<float2*>(C + (size_t)row * Nn + col) =
                    make_float2(v0, v1);
            if (row + 8 < M)
                *reinterpret_cast<float2*>(C + (size_t)(row + 8) * Nn + col) =
                    make_float2(v2, v3);
        }
    }
}

extern "C" void kernel_launch(void* const* d_in, const int* in_sizes, int n_in,
                              void* d_out, int out_size) {
    const float* x        = (const float*)d_in[0];
    const int*   adj_src  = (const int*)  d_in[1];
    const int*   adj_dst  = (const int*)  d_in[2];
    const float* adj_vals = (const float*)d_in[3];
    const float* eps      = (const float*)d_in[4];
    const float* W0       = (const float*)d_in[5];
    const float* W1       = (const float*)d_in[6];
    const float* gamma    = (const float*)d_in[7];
    const float* beta     = (const float*)d_in[8];
    const float* bn_mean  = (const float*)d_in[9];
    const float* bn_var   = (const float*)d_in[10];
    float* out = (float*)d_out;

    int N = in_sizes[0] / D_IN;
    int E = in_sizes[1];

    void* p;
    cudaGetSymbolAddress(&p, g_agg);   float* agg   = (float*)p;
    cudaGetSymbolAddress(&p, g_h);     float* h     = (float*)p;
    cudaGetSymbolAddress(&p, g_w0r);   float* w0r   = (float*)p;
    cudaGetSymbolAddress(&p, g_w1r);   float* w1r   = (float*)p;
    cudaGetSymbolAddress(&p, g_scale); float* scale = (float*)p;
    cudaGetSymbolAddress(&p, g_shift); float* shift = (float*)p;

    cudaFuncSetAttribute(pipe_gemm_kernel,
                         cudaFuncAttributeMaxDynamicSharedMemorySize, GEMM_SMEM);

    // 0) agg = eps * x
    int n4 = N * (D_IN / 4);
    init_agg_kernel<<<(n4 + 255) / 256, 256>>>(x, eps, n4);

    // 1) scatter edges into agg (vectorized L2 reductions)
    int work = E * (D_IN / 4);
    edge_scatter_kernel<<<(work + 255) / 256, 256>>>(x, adj_src, adj_dst, adj_vals, E);

    // 1b) round agg to tf32
    round_agg_kernel<<<(n4 + 255) / 256, 256>>>(n4);

    // 2) BN params + rounded weights
    bn_params_kernel<<<1, 256>>>(gamma, beta, bn_mean, bn_var);
    int wtot = D_IN * D_OUT + D_OUT * D_OUT;
    prep_w_kernel<<<(wtot + 255) / 256, 256>>>(W0, W1);

    dim3 grid(D_OUT / 128, (N + 127) / 128);
    // 3) h = round_tf32(relu(BN(agg @ W0)))
    pipe_gemm_kernel<<<grid, 128, GEMM_SMEM>>>(agg, w0r, h, N, D_OUT, D_IN,
                                               scale, shift, 1, 1);
    // 4) out = h @ W1
    pipe_gemm_kernel<<<grid, 128, GEMM_SMEM>>>(h, w1r, out, N, D_OUT, D_OUT,
                                               nullptr, nullptr, 0, 0);
}